// round 14
// baseline (speedup 1.0000x reference)
#include <cuda_runtime.h>
#include <cuda_bf16.h>
#include <cstdint>

#define BB 64
#define TT 512
#define EE 768
#define HH 256
#define VV 3072

__device__ float g_x[TT * BB * HH];   // xWxh laid out [t][b][h]
__device__ float g_h[BB * HH];        // final hidden

// bf16 hi/lo splits (prep kernel fills these)
__device__ __nv_bfloat16 g_embh[VV * EE];
__device__ __nv_bfloat16 g_embl[VV * EE];
__device__ __nv_bfloat16 g_wxh_h[HH * EE];   // TRANSPOSED: [n][k]
__device__ __nv_bfloat16 g_wxh_l[HH * EE];

// ---------- f32x2 helpers ----------
__device__ __forceinline__ unsigned long long pack2(float lo, float hi) {
    unsigned long long r;
    asm("mov.b64 %0, {%1, %2};" : "=l"(r) : "f"(lo), "f"(hi));
    return r;
}
__device__ __forceinline__ void unpack2(unsigned long long v, float& lo, float& hi) {
    asm("mov.b64 {%0, %1}, %2;" : "=f"(lo), "=f"(hi) : "l"(v));
}
__device__ __forceinline__ unsigned long long fma2(unsigned long long a,
                                                   unsigned long long b,
                                                   unsigned long long c) {
    unsigned long long d;
    asm("fma.rn.f32x2 %0, %1, %2, %3;" : "=l"(d) : "l"(a), "l"(b), "l"(c));
    return d;
}
__device__ __forceinline__ void cp16(uint32_t dst, const void* src) {
    asm volatile("cp.async.cg.shared.global [%0], [%1], 16;" :: "r"(dst), "l"(src));
}

// =====================================================================
// Prep: split emb and Wxh^T into bf16 hi/lo.
// =====================================================================
__global__ void prep_emb(const float* __restrict__ emb) {
    int i = blockIdx.x * blockDim.x + threadIdx.x;
    const int n = VV * EE;
    for (; i < n; i += gridDim.x * blockDim.x) {
        float v = emb[i];
        __nv_bfloat16 h = __float2bfloat16_rn(v);
        g_embh[i] = h;
        g_embl[i] = __float2bfloat16_rn(v - __bfloat162float(h));
    }
}
__global__ void prep_wxh(const float* __restrict__ Wxh) {
    int i = blockIdx.x * blockDim.x + threadIdx.x;
    const int n = HH * EE;
    for (; i < n; i += gridDim.x * blockDim.x) {
        int nn = i / EE, kk = i - nn * EE;
        float v = Wxh[kk * HH + nn];
        __nv_bfloat16 h = __float2bfloat16_rn(v);
        g_wxh_h[i] = h;
        g_wxh_l[i] = __float2bfloat16_rn(v - __bfloat162float(h));
    }
}

// =====================================================================
// Phase 1: g_x = gather(emb) @ Wxh via mma.sync bf16, 3-product split.
// (unchanged from R12 — at legacy-HMMA roofline)
// =====================================================================
#define SA   40
#define TSZ  (128 * SA * 2)     // 10240
#define STG  (4 * TSZ)          // 40960
#define GSM  (2 * STG)          // 81920

__device__ __forceinline__ uint32_t lds32(uint32_t a) {
    uint32_t x;
    asm volatile("ld.shared.b32 %0, [%1];" : "=r"(x) : "r"(a));
    return x;
}
__device__ __forceinline__ void mma_bf16(float* d, const uint32_t* a,
                                         uint32_t b0, uint32_t b1) {
    asm volatile(
        "mma.sync.aligned.m16n8k16.row.col.f32.bf16.bf16.f32 "
        "{%0,%1,%2,%3}, {%4,%5,%6,%7}, {%8,%9}, {%0,%1,%2,%3};"
        : "+f"(d[0]), "+f"(d[1]), "+f"(d[2]), "+f"(d[3])
        : "r"(a[0]), "r"(a[1]), "r"(a[2]), "r"(a[3]), "r"(b0), "r"(b1));
}

__global__ __launch_bounds__(256, 2)
void gemm_mma(const int* __restrict__ idx) {
    extern __shared__ __align__(16) char smraw[];
    __shared__ int idx_s[128];

    const int tid = threadIdx.x;
    const int bm = blockIdx.y;   // 0..255
    const int bn = blockIdx.x;   // 0..1

    if (tid < 128) idx_s[tid] = idx[bm * 128 + tid];
    __syncthreads();

    const uint32_t sb = (uint32_t)__cvta_generic_to_shared(smraw);

    const int lr = tid & 127;
    const int lt = tid >> 7;
    const __nv_bfloat16 *srcH, *srcL;
    if (lt == 0) {
        long r = idx_s[lr];
        srcH = g_embh + r * EE;
        srcL = g_embl + r * EE;
    } else {
        size_t n = (size_t)(bn * 128 + lr);
        srcH = g_wxh_h + n * EE;
        srcL = g_wxh_l + n * EE;
    }
    const uint32_t dstH = sb + lt * 20480 + lr * 80;
    const uint32_t dstL = dstH + 10240;

#define ISSUE(n, s)                                                          \
    do {                                                                     \
        const __nv_bfloat16* sh = srcH + (n) * 32;                           \
        const __nv_bfloat16* sl = srcL + (n) * 32;                           \
        const uint32_t so = (s) * (uint32_t)STG;                             \
        cp16(dstH + so,      sh);      cp16(dstH + so + 16, sh + 8);         \
        cp16(dstH + so + 32, sh + 16); cp16(dstH + so + 48, sh + 24);        \
        cp16(dstL + so,      sl);      cp16(dstL + so + 16, sl + 8);         \
        cp16(dstL + so + 32, sl + 16); cp16(dstL + so + 48, sl + 24);        \
        asm volatile("cp.async.commit_group;");                              \
    } while (0)

    const int lane = tid & 31;
    const int w  = tid >> 5;
    const int wm = w & 3;
    const int wn = w >> 2;
    const int g  = lane >> 2;
    const int q  = lane & 3;

    float acc[2][8][4];
#pragma unroll
    for (int mi = 0; mi < 2; mi++)
#pragma unroll
        for (int nb = 0; nb < 8; nb++)
#pragma unroll
            for (int e = 0; e < 4; e++) acc[mi][nb][e] = 0.f;

    const int NT = EE / 32;   // 24

    ISSUE(0, 0);

    for (int i = 0; i < NT; i++) {
        const int s = i & 1;
        asm volatile("cp.async.wait_group 0;");
        __syncthreads();
        if (i + 1 < NT) ISSUE(i + 1, s ^ 1);

        const uint32_t aB = sb + s * (uint32_t)STG;
        const uint32_t bB = aB + 20480;

#pragma unroll
        for (int ks = 0; ks < 2; ks++) {
            const int kq = ks * 16 + 2 * q;

            uint32_t ah[2][4], al[2][4];
#pragma unroll
            for (int mi = 0; mi < 2; mi++) {
                const int r = wm * 32 + mi * 16 + g;
                const uint32_t o00 = aB + (uint32_t)((r * SA + kq) * 2);
                const uint32_t o10 = aB + (uint32_t)(((r + 8) * SA + kq) * 2);
                ah[mi][0] = lds32(o00);
                ah[mi][1] = lds32(o10);
                ah[mi][2] = lds32(o00 + 16);
                ah[mi][3] = lds32(o10 + 16);
                al[mi][0] = lds32(o00 + 10240);
                al[mi][1] = lds32(o10 + 10240);
                al[mi][2] = lds32(o00 + 16 + 10240);
                al[mi][3] = lds32(o10 + 16 + 10240);
            }

#pragma unroll
            for (int nb = 0; nb < 8; nb++) {
                const int n = wn * 64 + nb * 8 + g;
                const uint32_t ob = bB + (uint32_t)((n * SA + kq) * 2);
                uint32_t bh0 = lds32(ob);
                uint32_t bh1 = lds32(ob + 16);
                uint32_t bl0 = lds32(ob + 10240);
                uint32_t bl1 = lds32(ob + 16 + 10240);
#pragma unroll
                for (int mi = 0; mi < 2; mi++) {
                    mma_bf16(acc[mi][nb], ah[mi], bh0, bh1);
                    mma_bf16(acc[mi][nb], ah[mi], bl0, bl1);
                    mma_bf16(acc[mi][nb], al[mi], bh0, bh1);
                }
            }
        }
        __syncthreads();
    }
#undef ISSUE

#pragma unroll
    for (int mi = 0; mi < 2; mi++) {
#pragma unroll
        for (int nb = 0; nb < 8; nb++) {
            const int m0 = bm * 128 + wm * 32 + mi * 16 + g;
            const int cc = bn * 128 + wn * 64 + nb * 8 + 2 * q;
            {
                const int b = m0 >> 9, t = m0 & 511;
                float2 v = make_float2(acc[mi][nb][0], acc[mi][nb][1]);
                *reinterpret_cast<float2*>(
                    g_x + (size_t)t * (BB * HH) + b * HH + cc) = v;
            }
            {
                const int m1 = m0 + 8;
                const int b = m1 >> 9, t = m1 & 511;
                float2 v = make_float2(acc[mi][nb][2], acc[mi][nb][3]);
                *reinterpret_cast<float2*>(
                    g_x + (size_t)t * (BB * HH) + b * HH + cc) = v;
            }
        }
    }
}

// =====================================================================
// Phase 2: recurrent scan, TWO BATCHES PER CLUSTER.
// 32 clusters x 2 CTAs x 512 threads. Whh regs shared across batches.
// Thread map: jl = tid&127, c = tid>>7 (4 chunks of 64 rows,
// warp-uniform -> broadcast LDS). w2[32] u64, static indexing.
// Per step: both batches' partials -> psum (2 arrays) -> ONE
// __syncthreads -> c0 tail for both -> ONE barrier.cluster.
// Exchange semantics per batch = proven R2/R12 pattern.
// =====================================================================
__global__ __launch_bounds__(512, 1) __cluster_dims__(2, 1, 1)
void rnn_scan(const float* __restrict__ Whh, const float* __restrict__ Bh) {
    __shared__ __align__(16) float hbuf[2][2][256];   // [batch][buf][j]
    __shared__ float psum[2][3][128];                 // [batch][c-1][jl]

    const int tid = threadIdx.x;
    const int b0 = (blockIdx.x >> 1) * 2;   // first batch of this cluster
    uint32_t rank;
    asm("mov.u32 %0, %%cluster_ctarank;" : "=r"(rank));
    const uint32_t prank = rank ^ 1u;

    const int jl = tid & 127;
    const int c  = tid >> 7;            // 0..3, warp-uniform
    const int j  = (int)rank * 128 + jl;
    const int i0 = c * 64;

    // 64 weights (rows i0..i0+63, col j) as 32 f32x2 regs, STATIC indices
    unsigned long long w2[32];
#pragma unroll
    for (int p = 0; p < 32; p++) {
        int i = i0 + 2 * p;
        w2[p] = pack2(Whh[i * HH + j], Whh[(i + 1) * HH + j]);
    }
    float bh = 0.f;
    if (c == 0) bh = Bh[j];

    const uint32_t hb_base = (uint32_t)__cvta_generic_to_shared(&hbuf[0][0][0]);

    // peer addresses of hbuf[bt][buf][j]
    uint32_t peer_h[2][2];
#pragma unroll
    for (int bt = 0; bt < 2; bt++)
#pragma unroll
        for (int bb = 0; bb < 2; bb++) {
            uint32_t lh = hb_base + (bt * 2 + bb) * 1024 + j * 4;
            asm("mapa.shared::cluster.u32 %0, %1, %2;"
                : "=r"(peer_h[bt][bb]) : "r"(lh), "r"(prank));
        }

    if (tid < 256) { hbuf[0][0][tid] = 0.f; hbuf[1][0][tid] = 0.f; }
    __syncthreads();
    asm volatile("barrier.cluster.arrive.aligned;" ::: "memory");
    asm volatile("barrier.cluster.wait.aligned;"   ::: "memory");

    const float* xptr0 = g_x + b0 * HH + j;
    const float* xptr1 = g_x + (b0 + 1) * HH + j;
    float xv0 = 0.f, xv1 = 0.f;
    if (c == 0) { xv0 = xptr0[0]; xv1 = xptr1[0]; }

    for (int t = 0; t < TT; t++) {
        const int cur = t & 1;
        const int nb  = cur ^ 1;

        float x0 = 0.f, x1 = 0.f;
        if (c == 0) {
            x0 = xv0; x1 = xv1;
            if (t + 1 < TT) {
                xv0 = xptr0[(size_t)(t + 1) * (BB * HH)];
                xv1 = xptr1[(size_t)(t + 1) * (BB * HH)];
            }
        }

        // ---- batch 0 partial ----
        const uint32_t ha0 = hb_base + cur * 1024 + i0 * 4;
        unsigned long long a0 = 0ull, a1 = 0ull;
#pragma unroll
        for (int p = 0; p < 8; p++) {
            unsigned long long h0, h1, h2, h3;
            asm volatile("ld.shared.v2.u64 {%0,%1}, [%2];"
                         : "=l"(h0), "=l"(h1) : "r"(ha0 + p * 32));
            asm volatile("ld.shared.v2.u64 {%0,%1}, [%2];"
                         : "=l"(h2), "=l"(h3) : "r"(ha0 + p * 32 + 16));
            a0 = fma2(w2[4 * p + 0], h0, a0);
            a1 = fma2(w2[4 * p + 1], h1, a1);
            a0 = fma2(w2[4 * p + 2], h2, a0);
            a1 = fma2(w2[4 * p + 3], h3, a1);
        }
        float l0, u0, l1, u1;
        unpack2(a0, l0, u0); unpack2(a1, l1, u1);
        float part0 = (l0 + u0) + (l1 + u1);

        // ---- batch 1 partial ----
        const uint32_t ha1 = hb_base + (2 + cur) * 1024 + i0 * 4;
        a0 = 0ull; a1 = 0ull;
#pragma unroll
        for (int p = 0; p < 8; p++) {
            unsigned long long h0, h1, h2, h3;
            asm volatile("ld.shared.v2.u64 {%0,%1}, [%2];"
                         : "=l"(h0), "=l"(h1) : "r"(ha1 + p * 32));
            asm volatile("ld.shared.v2.u64 {%0,%1}, [%2];"
                         : "=l"(h2), "=l"(h3) : "r"(ha1 + p * 32 + 16));
            a0 = fma2(w2[4 * p + 0], h0, a0);
            a1 = fma2(w2[4 * p + 1], h1, a1);
            a0 = fma2(w2[4 * p + 2], h2, a0);
            a1 = fma2(w2[4 * p + 3], h3, a1);
        }
        unpack2(a0, l0, u0); unpack2(a1, l1, u1);
        float part1 = (l0 + u0) + (l1 + u1);

        if (c > 0) {
            psum[0][c - 1][jl] = part0;
            psum[1][c - 1][jl] = part1;
        }
        __syncthreads();

        if (c == 0) {
            float s0 = part0 + psum[0][0][jl] + psum[0][1][jl]
                             + psum[0][2][jl] + x0 + bh;
            float s1 = part1 + psum[1][0][jl] + psum[1][1][jl]
                             + psum[1][2][jl] + x1 + bh;
            float hn0 = tanhf(s0);
            float hn1 = tanhf(s1);
            hbuf[0][nb][j] = hn0;
            hbuf[1][nb][j] = hn1;
            asm volatile("st.shared::cluster.f32 [%0], %1;"
                         :: "r"(peer_h[0][nb]), "f"(hn0) : "memory");
            asm volatile("st.shared::cluster.f32 [%0], %1;"
                         :: "r"(peer_h[1][nb]), "f"(hn1) : "memory");
            if (t == TT - 1) {
                g_h[b0 * HH + j]       = hn0;
                g_h[(b0 + 1) * HH + j] = hn1;
            }
        }

        asm volatile("barrier.cluster.arrive.aligned;" ::: "memory");
        asm volatile("barrier.cluster.wait.aligned;"   ::: "memory");
    }
    // final iteration's cluster barrier fences in-flight remote stores
}

// =====================================================================
// Phase 3: out[b][v] = g_h[b] @ Wy + By.  2 batches per CTA.
// =====================================================================
__global__ __launch_bounds__(256)
void out_proj(const float* __restrict__ Wy, const float* __restrict__ By,
              float* __restrict__ out, int out_size) {
    if (blockIdx.x == 384) {
        if (out_size >= BB * VV + BB * HH) {
            for (int i = threadIdx.x; i < BB * HH; i += 256)
                out[BB * VV + i] = g_h[i];
        }
        return;
    }
    __shared__ float hs[2][HH];
    const int b0 = (blockIdx.x / 12) * 2;
    const int vt = blockIdx.x % 12;
    const int v  = vt * 256 + threadIdx.x;

    hs[0][threadIdx.x] = g_h[b0 * HH + threadIdx.x];
    hs[1][threadIdx.x] = g_h[(b0 + 1) * HH + threadIdx.x];
    __syncthreads();

    float acc0 = 0.f, acc1 = 0.f;
#pragma unroll 8
    for (int h = 0; h < HH; h++) {
        float w = Wy[(size_t)h * VV + v];
        acc0 += hs[0][h] * w;
        acc1 += hs[1][h] * w;
    }
    float by = By[v];
    out[(size_t)b0 * VV + v]       = acc0 + by;
    out[(size_t)(b0 + 1) * VV + v] = acc1 + by;
}

// =====================================================================
extern "C" void kernel_launch(void* const* d_in, const int* in_sizes, int n_in,
                              void* d_out, int out_size) {
    const int*   idx = (const int*)d_in[0];
    const float* emb = (const float*)d_in[1];
    const float* Wxh = (const float*)d_in[2];
    const float* Whh = (const float*)d_in[3];
    const float* Wy  = (const float*)d_in[4];
    const float* By  = (const float*)d_in[5];
    const float* Bh  = (const float*)d_in[6];
    float* out = (float*)d_out;

    static bool attr_set = false;
    if (!attr_set) {
        cudaFuncSetAttribute(gemm_mma,
                             cudaFuncAttributeMaxDynamicSharedMemorySize,
                             GSM);
        attr_set = true;
    }

    prep_emb<<<2048, 256>>>(emb);
    prep_wxh<<<192, 256>>>(Wxh);
    gemm_mma<<<dim3(2, 256), 256, GSM>>>(idx);
    rnn_scan<<<64, 512>>>(Whh, Bh);
    out_proj<<<385, 256>>>(Wy, By, out, out_size);
}

// round 15
// speedup vs baseline: 1.2359x; 1.2359x over previous
#include <cuda_runtime.h>
#include <cuda_bf16.h>
#include <cstdint>

#define BB 64
#define TT 512
#define EE 768
#define HH 256
#define VV 3072

__device__ float g_x[TT * BB * HH];   // xWxh laid out [t][b][h]
__device__ float g_h[BB * HH];        // final hidden

// bf16 hi/lo splits (prep kernel fills these)
__device__ __nv_bfloat16 g_embh[VV * EE];
__device__ __nv_bfloat16 g_embl[VV * EE];
__device__ __nv_bfloat16 g_wxh_h[HH * EE];   // TRANSPOSED: [n][k]
__device__ __nv_bfloat16 g_wxh_l[HH * EE];

// ---------- f32x2 helpers ----------
__device__ __forceinline__ unsigned long long pack2(float lo, float hi) {
    unsigned long long r;
    asm("mov.b64 %0, {%1, %2};" : "=l"(r) : "f"(lo), "f"(hi));
    return r;
}
__device__ __forceinline__ void unpack2(unsigned long long v, float& lo, float& hi) {
    asm("mov.b64 {%0, %1}, %2;" : "=f"(lo), "=f"(hi) : "l"(v));
}
__device__ __forceinline__ unsigned long long fma2(unsigned long long a,
                                                   unsigned long long b,
                                                   unsigned long long c) {
    unsigned long long d;
    asm("fma.rn.f32x2 %0, %1, %2, %3;" : "=l"(d) : "l"(a), "l"(b), "l"(c));
    return d;
}
__device__ __forceinline__ void cp16(uint32_t dst, const void* src) {
    asm volatile("cp.async.cg.shared.global [%0], [%1], 16;" :: "r"(dst), "l"(src));
}

// =====================================================================
// Prep: split emb and Wxh^T into bf16 hi/lo.
// =====================================================================
__global__ void prep_emb(const float* __restrict__ emb) {
    int i = blockIdx.x * blockDim.x + threadIdx.x;
    const int n = VV * EE;
    for (; i < n; i += gridDim.x * blockDim.x) {
        float v = emb[i];
        __nv_bfloat16 h = __float2bfloat16_rn(v);
        g_embh[i] = h;
        g_embl[i] = __float2bfloat16_rn(v - __bfloat162float(h));
    }
}
__global__ void prep_wxh(const float* __restrict__ Wxh) {
    int i = blockIdx.x * blockDim.x + threadIdx.x;
    const int n = HH * EE;
    for (; i < n; i += gridDim.x * blockDim.x) {
        int nn = i / EE, kk = i - nn * EE;
        float v = Wxh[kk * HH + nn];
        __nv_bfloat16 h = __float2bfloat16_rn(v);
        g_wxh_h[i] = h;
        g_wxh_l[i] = __float2bfloat16_rn(v - __bfloat162float(h));
    }
}

// =====================================================================
// Phase 1: g_x = gather(emb) @ Wxh via mma.sync bf16, 3-product split.
// (R12 version — at legacy-HMMA roofline, ~145us)
// =====================================================================
#define SA   40
#define TSZ  (128 * SA * 2)     // 10240
#define STG  (4 * TSZ)          // 40960
#define GSM  (2 * STG)          // 81920

__device__ __forceinline__ uint32_t lds32(uint32_t a) {
    uint32_t x;
    asm volatile("ld.shared.b32 %0, [%1];" : "=r"(x) : "r"(a));
    return x;
}
__device__ __forceinline__ void mma_bf16(float* d, const uint32_t* a,
                                         uint32_t b0, uint32_t b1) {
    asm volatile(
        "mma.sync.aligned.m16n8k16.row.col.f32.bf16.bf16.f32 "
        "{%0,%1,%2,%3}, {%4,%5,%6,%7}, {%8,%9}, {%0,%1,%2,%3};"
        : "+f"(d[0]), "+f"(d[1]), "+f"(d[2]), "+f"(d[3])
        : "r"(a[0]), "r"(a[1]), "r"(a[2]), "r"(a[3]), "r"(b0), "r"(b1));
}

__global__ __launch_bounds__(256, 2)
void gemm_mma(const int* __restrict__ idx) {
    extern __shared__ __align__(16) char smraw[];
    __shared__ int idx_s[128];

    const int tid = threadIdx.x;
    const int bm = blockIdx.y;   // 0..255
    const int bn = blockIdx.x;   // 0..1

    if (tid < 128) idx_s[tid] = idx[bm * 128 + tid];
    __syncthreads();

    const uint32_t sb = (uint32_t)__cvta_generic_to_shared(smraw);

    const int lr = tid & 127;
    const int lt = tid >> 7;
    const __nv_bfloat16 *srcH, *srcL;
    if (lt == 0) {
        long r = idx_s[lr];
        srcH = g_embh + r * EE;
        srcL = g_embl + r * EE;
    } else {
        size_t n = (size_t)(bn * 128 + lr);
        srcH = g_wxh_h + n * EE;
        srcL = g_wxh_l + n * EE;
    }
    const uint32_t dstH = sb + lt * 20480 + lr * 80;
    const uint32_t dstL = dstH + 10240;

#define ISSUE(n, s)                                                          \
    do {                                                                     \
        const __nv_bfloat16* sh = srcH + (n) * 32;                           \
        const __nv_bfloat16* sl = srcL + (n) * 32;                           \
        const uint32_t so = (s) * (uint32_t)STG;                             \
        cp16(dstH + so,      sh);      cp16(dstH + so + 16, sh + 8);         \
        cp16(dstH + so + 32, sh + 16); cp16(dstH + so + 48, sh + 24);        \
        cp16(dstL + so,      sl);      cp16(dstL + so + 16, sl + 8);         \
        cp16(dstL + so + 32, sl + 16); cp16(dstL + so + 48, sl + 24);        \
        asm volatile("cp.async.commit_group;");                              \
    } while (0)

    const int lane = tid & 31;
    const int w  = tid >> 5;
    const int wm = w & 3;
    const int wn = w >> 2;
    const int g  = lane >> 2;
    const int q  = lane & 3;

    float acc[2][8][4];
#pragma unroll
    for (int mi = 0; mi < 2; mi++)
#pragma unroll
        for (int nb = 0; nb < 8; nb++)
#pragma unroll
            for (int e = 0; e < 4; e++) acc[mi][nb][e] = 0.f;

    const int NT = EE / 32;   // 24

    ISSUE(0, 0);

    for (int i = 0; i < NT; i++) {
        const int s = i & 1;
        asm volatile("cp.async.wait_group 0;");
        __syncthreads();
        if (i + 1 < NT) ISSUE(i + 1, s ^ 1);

        const uint32_t aB = sb + s * (uint32_t)STG;
        const uint32_t bB = aB + 20480;

#pragma unroll
        for (int ks = 0; ks < 2; ks++) {
            const int kq = ks * 16 + 2 * q;

            uint32_t ah[2][4], al[2][4];
#pragma unroll
            for (int mi = 0; mi < 2; mi++) {
                const int r = wm * 32 + mi * 16 + g;
                const uint32_t o00 = aB + (uint32_t)((r * SA + kq) * 2);
                const uint32_t o10 = aB + (uint32_t)(((r + 8) * SA + kq) * 2);
                ah[mi][0] = lds32(o00);
                ah[mi][1] = lds32(o10);
                ah[mi][2] = lds32(o00 + 16);
                ah[mi][3] = lds32(o10 + 16);
                al[mi][0] = lds32(o00 + 10240);
                al[mi][1] = lds32(o10 + 10240);
                al[mi][2] = lds32(o00 + 16 + 10240);
                al[mi][3] = lds32(o10 + 16 + 10240);
            }

#pragma unroll
            for (int nb = 0; nb < 8; nb++) {
                const int n = wn * 64 + nb * 8 + g;
                const uint32_t ob = bB + (uint32_t)((n * SA + kq) * 2);
                uint32_t bh0 = lds32(ob);
                uint32_t bh1 = lds32(ob + 16);
                uint32_t bl0 = lds32(ob + 10240);
                uint32_t bl1 = lds32(ob + 16 + 10240);
#pragma unroll
                for (int mi = 0; mi < 2; mi++) {
                    mma_bf16(acc[mi][nb], ah[mi], bh0, bh1);
                    mma_bf16(acc[mi][nb], ah[mi], bl0, bl1);
                    mma_bf16(acc[mi][nb], al[mi], bh0, bh1);
                }
            }
        }
        __syncthreads();
    }
#undef ISSUE

#pragma unroll
    for (int mi = 0; mi < 2; mi++) {
#pragma unroll
        for (int nb = 0; nb < 8; nb++) {
            const int m0 = bm * 128 + wm * 32 + mi * 16 + g;
            const int cc = bn * 128 + wn * 64 + nb * 8 + 2 * q;
            {
                const int b = m0 >> 9, t = m0 & 511;
                float2 v = make_float2(acc[mi][nb][0], acc[mi][nb][1]);
                *reinterpret_cast<float2*>(
                    g_x + (size_t)t * (BB * HH) + b * HH + cc) = v;
            }
            {
                const int m1 = m0 + 8;
                const int b = m1 >> 9, t = m1 & 511;
                float2 v = make_float2(acc[mi][nb][2], acc[mi][nb][3]);
                *reinterpret_cast<float2*>(
                    g_x + (size_t)t * (BB * HH) + b * HH + cc) = v;
            }
        }
    }
}

// =====================================================================
// Phase 2: recurrent scan — the PROVEN R2 structure (best measured:
// ~400us). Cluster of 2 CTAs per batch, 512 thr/CTA, grid 128.
// jl = tid&127, c = tid>>7 (4 chunks of 64 rows, warp-uniform ->
// broadcast LDS, zero conflicts). w2[32] u64, 100% static indexing.
// Per step: partials -> psum -> __syncthreads -> c0 tail (sum, tanh,
// local store + peer DSMEM store) -> ONE barrier.cluster.
// =====================================================================
__global__ __launch_bounds__(512, 1) __cluster_dims__(2, 1, 1)
void rnn_scan(const float* __restrict__ Whh, const float* __restrict__ Bh) {
    __shared__ __align__(16) float hbuf[2][256];
    __shared__ __align__(8) float psum[3][128];

    const int tid = threadIdx.x;
    const int b = blockIdx.x >> 1;
    uint32_t rank;
    asm("mov.u32 %0, %%cluster_ctarank;" : "=r"(rank));
    const uint32_t prank = rank ^ 1u;

    const int jl = tid & 127;
    const int c  = tid >> 7;            // 0..3, warp-uniform
    const int j  = (int)rank * 128 + jl;
    const int i0 = c * 64;

    // 64 weights (rows i0..i0+63, col j) as 32 f32x2 regs, STATIC indices
    unsigned long long w2[32];
#pragma unroll
    for (int p = 0; p < 32; p++) {
        int i = i0 + 2 * p;
        w2[p] = pack2(Whh[i * HH + j], Whh[(i + 1) * HH + j]);
    }
    float bh = 0.f;
    if (c == 0) bh = Bh[j];

    const uint32_t hb_base = (uint32_t)__cvta_generic_to_shared(&hbuf[0][0]);
    const uint32_t ps_base = (uint32_t)__cvta_generic_to_shared(&psum[0][0]);

    uint32_t peer_h[2];
#pragma unroll
    for (int bb = 0; bb < 2; bb++) {
        uint32_t lh = hb_base + bb * 1024 + j * 4;
        asm("mapa.shared::cluster.u32 %0, %1, %2;"
            : "=r"(peer_h[bb]) : "r"(lh), "r"(prank));
    }

    if (tid < 256) hbuf[0][tid] = 0.f;
    __syncthreads();
    asm volatile("barrier.cluster.arrive.aligned;" ::: "memory");
    asm volatile("barrier.cluster.wait.aligned;"   ::: "memory");

    const float* xptr = g_x + b * HH + j;
    float xv_cur = 0.f;
    if (c == 0) xv_cur = xptr[0];

    for (int t = 0; t < TT; t++) {
        const int cur = t & 1;
        const int nb  = cur ^ 1;

        float xv = 0.f;
        if (c == 0) {
            xv = xv_cur;
            if (t + 1 < TT) xv_cur = xptr[(size_t)(t + 1) * (BB * HH)];
        }

        // partial = sum_{i in chunk of 64} Whh[i][j] * h[i]
        const uint32_t ha = hb_base + cur * 1024 + i0 * 4;
        unsigned long long acc0 = 0ull, acc1 = 0ull;
#pragma unroll
        for (int p = 0; p < 8; p++) {
            unsigned long long h0, h1, h2, h3;
            asm volatile("ld.shared.v2.u64 {%0,%1}, [%2];"
                         : "=l"(h0), "=l"(h1) : "r"(ha + p * 32));
            asm volatile("ld.shared.v2.u64 {%0,%1}, [%2];"
                         : "=l"(h2), "=l"(h3) : "r"(ha + p * 32 + 16));
            acc0 = fma2(w2[4 * p + 0], h0, acc0);
            acc1 = fma2(w2[4 * p + 1], h1, acc1);
            acc0 = fma2(w2[4 * p + 2], h2, acc0);
            acc1 = fma2(w2[4 * p + 3], h3, acc1);
        }
        float l0, u0, l1, u1;
        unpack2(acc0, l0, u0); unpack2(acc1, l1, u1);
        float part = (l0 + u0) + (l1 + u1);

        if (c > 0) psum[c - 1][jl] = part;
        __syncthreads();

        if (c == 0) {
            // psum[0][jl], psum[1][jl] adjacent? no — read v2 from
            // psum[0..1][jl] is strided; use two scalar + one pair:
            float p0 = psum[0][jl];
            float p1 = psum[1][jl];
            float p2 = psum[2][jl];
            float s = part + ((p0 + p1) + (p2 + xv)) + bh;
            float hn = tanhf(s);
            hbuf[nb][j] = hn;                               // local copy
            asm volatile("st.shared::cluster.f32 [%0], %1;" // peer copy
                         :: "r"(peer_h[nb]), "f"(hn) : "memory");
            if (t == TT - 1) g_h[b * HH + j] = hn;
        }

        asm volatile("barrier.cluster.arrive.aligned;" ::: "memory");
        asm volatile("barrier.cluster.wait.aligned;"   ::: "memory");
    }
    // final iteration's cluster barrier fences in-flight remote stores
    (void)ps_base;
}

// =====================================================================
// Phase 3: out[b][v] = g_h[b] @ Wy + By.  2 batches per CTA.
// =====================================================================
__global__ __launch_bounds__(256)
void out_proj(const float* __restrict__ Wy, const float* __restrict__ By,
              float* __restrict__ out, int out_size) {
    if (blockIdx.x == 384) {
        if (out_size >= BB * VV + BB * HH) {
            for (int i = threadIdx.x; i < BB * HH; i += 256)
                out[BB * VV + i] = g_h[i];
        }
        return;
    }
    __shared__ float hs[2][HH];
    const int b0 = (blockIdx.x / 12) * 2;
    const int vt = blockIdx.x % 12;
    const int v  = vt * 256 + threadIdx.x;

    hs[0][threadIdx.x] = g_h[b0 * HH + threadIdx.x];
    hs[1][threadIdx.x] = g_h[(b0 + 1) * HH + threadIdx.x];
    __syncthreads();

    float acc0 = 0.f, acc1 = 0.f;
#pragma unroll 8
    for (int h = 0; h < HH; h++) {
        float w = Wy[(size_t)h * VV + v];
        acc0 += hs[0][h] * w;
        acc1 += hs[1][h] * w;
    }
    float by = By[v];
    out[(size_t)b0 * VV + v]       = acc0 + by;
    out[(size_t)(b0 + 1) * VV + v] = acc1 + by;
}

// =====================================================================
extern "C" void kernel_launch(void* const* d_in, const int* in_sizes, int n_in,
                              void* d_out, int out_size) {
    const int*   idx = (const int*)d_in[0];
    const float* emb = (const float*)d_in[1];
    const float* Wxh = (const float*)d_in[2];
    const float* Whh = (const float*)d_in[3];
    const float* Wy  = (const float*)d_in[4];
    const float* By  = (const float*)d_in[5];
    const float* Bh  = (const float*)d_in[6];
    float* out = (float*)d_out;

    static bool attr_set = false;
    if (!attr_set) {
        cudaFuncSetAttribute(gemm_mma,
                             cudaFuncAttributeMaxDynamicSharedMemorySize,
                             GSM);
        attr_set = true;
    }

    prep_emb<<<2048, 256>>>(emb);
    prep_wxh<<<192, 256>>>(Wxh);
    gemm_mma<<<dim3(2, 256), 256, GSM>>>(idx);
    rnn_scan<<<128, 512>>>(Whh, Bh);
    out_proj<<<385, 256>>>(Wy, By, out, out_size);
}